// round 1
// baseline (speedup 1.0000x reference)
#include <cuda_runtime.h>
#include <cuda_bf16.h>
#include <math.h>

// Problem constants (fixed by setup_inputs)
#define Bz   2
#define C    64
#define H    128
#define W    128
#define OUT  256
#define TILE 64          // pixels per block (one row segment)
#define NTHR 256

// smem layout (in floats)
#define OFF_W1   0                    // w1s[c*68+i], 64x68
#define OFF_W2   4352                 // w2s[c*68+i], 64x(64 pad 68)
#define OFF_WC   8704                 // wcp[ed*68+c], 32x(64 pad 68)
#define OFF_WE   10880                // wes[(e*64+c)*8+d], 2048 (original layout)
#define OFF_WRT  12928                // wrT[i*4+e], 256
#define OFF_WOT  13184                // woT[i*2+o], 128
#define OFF_B1   13312                // 64
#define OFF_B2   13376                // 64
#define OFF_BR   13440                // 4
#define OFF_BO   13444                // 2
#define OFF_INP  13448                // inps[p*76 + i], 64x76 (aliased: embs[p*65+i])
#define OFF_HID  18312                // hidfea: hidden[p*64+c] / fea0[p*68+c], 64x68
#define OFF_RS   22664                // rs[p*5+e], 64x5
#define OFF_OFS  22984                // offs[p*3+o], 64x3
#define OFF_CMP  23176                // comps[p*9+d], 64x9
#define SMEM_FLOATS 23752
#define SMEM_BYTES (SMEM_FLOATS * 4)

#define INP_S 76
#define EMB_S 65
#define FEA_S 68

__device__ __forceinline__ float4 ld4(const float* p) {
    return *reinterpret_cast<const float4*>(p);
}

__device__ __forceinline__ float bilin(const float* __restrict__ img, float fx, float fy) {
    float x0f = floorf(fx), y0f = floorf(fy);
    float wx1 = fx - x0f, wy1 = fy - y0f;
    float wx0 = 1.0f - wx1, wy0 = 1.0f - wy1;
    int x0 = (int)x0f, y0 = (int)y0f;
    int xi0 = min(max(x0, 0), W - 1), yi0 = min(max(y0, 0), H - 1);
    int xi1 = min(max(x0 + 1, 0), W - 1), yi1 = min(max(y0 + 1, 0), H - 1);
    bool vx0 = (x0f >= 0.0f) && (x0f <= (float)(W - 1));
    bool vx1 = (x0f >= -1.0f) && (x0f <= (float)(W - 2));
    bool vy0 = (y0f >= 0.0f) && (y0f <= (float)(H - 1));
    bool vy1 = (y0f >= -1.0f) && (y0f <= (float)(H - 2));
    float v00 = (vx0 && vy0) ? __ldg(img + yi0 * W + xi0) : 0.0f;
    float v10 = (vx1 && vy0) ? __ldg(img + yi0 * W + xi1) : 0.0f;
    float v01 = (vx0 && vy1) ? __ldg(img + yi1 * W + xi0) : 0.0f;
    float v11 = (vx1 && vy1) ? __ldg(img + yi1 * W + xi1) : 0.0f;
    return v00 * (wx0 * wy0) + v10 * (wx1 * wy0) + v01 * (wx0 * wy1) + v11 * (wx1 * wy1);
}

__global__ __launch_bounds__(NTHR, 2)
void SCAB_upsample_20650202759886_kernel(
    const float* __restrict__ x,
    const float* __restrict__ wcmp,   // (4,8,64)
    const float* __restrict__ wexp,   // (4,64,8)
    const float* __restrict__ w1,     // (64,68)
    const float* __restrict__ b1,
    const float* __restrict__ w2,     // (64,64)
    const float* __restrict__ b2,
    const float* __restrict__ wr,     // (4,64)
    const float* __restrict__ br,
    const float* __restrict__ wo,     // (2,64)
    const float* __restrict__ bo,
    float* __restrict__ out)
{
    extern __shared__ float sm[];
    float* w1s  = sm + OFF_W1;
    float* w2s  = sm + OFF_W2;
    float* wcp  = sm + OFF_WC;
    float* wes  = sm + OFF_WE;
    float* wrTs = sm + OFF_WRT;
    float* woTs = sm + OFF_WOT;
    float* b1s  = sm + OFF_B1;
    float* b2s  = sm + OFF_B2;
    float* brs  = sm + OFF_BR;
    float* bos  = sm + OFF_BO;
    float* inps = sm + OFF_INP;   // also embs
    float* embs = sm + OFF_INP;
    float* hidf = sm + OFF_HID;   // hidden / fea0 union
    float* rs   = sm + OFF_RS;
    float* offs = sm + OFF_OFS;
    float* cmps = sm + OFF_CMP;

    const int t  = threadIdx.x;
    const int oy = blockIdx.y;
    const int bz = blockIdx.z;
    const int ox0 = blockIdx.x * TILE;

    // ---- stage weights ----
    for (int i = t; i < 64 * 68; i += NTHR) w1s[i] = w1[i];
    for (int i = t; i < 64 * 64; i += NTHR) { int c = i >> 6, k = i & 63; w2s[c * 68 + k] = w2[i]; }
    for (int i = t; i < 32 * 64; i += NTHR) { int ed = i >> 6, c = i & 63; wcp[ed * 68 + c] = wcmp[i]; }
    for (int i = t; i < 2048;    i += NTHR) wes[i] = wexp[i];
    if (t < 256) { int e = t >> 6, k = t & 63; wrTs[k * 4 + e] = wr[t]; }
    if (t < 128) { int o = t >> 6, k = t & 63; woTs[k * 2 + o] = wo[t]; }
    if (t < 64) { b1s[t] = b1[t]; b2s[t] = b2[t]; }
    if (t < 4) brs[t] = br[t];
    if (t < 2) bos[t] = bo[t];
    __syncthreads();

    const float inv127 = 2.0f / 127.0f;

    // ---- phase 1: coords + pre_fea sample ----
    {
        const int p  = t & 63;
        const int cb = t >> 6;
        const int ox = ox0 + p;
        float gx = ((ox + 0.5f) / 2.0f - 0.5f) * inv127 - 1.0f;
        float gy = ((oy + 0.5f) / 2.0f - 0.5f) * inv127 - 1.0f;
        float fx = ((gx + 1.0f) * (float)W - 1.0f) * 0.5f;
        float fy = ((gy + 1.0f) * (float)H - 1.0f) * 0.5f;
        if (cb == 0) {
            float ah = (oy + 0.5f) / 2.0f;
            float aw = (ox + 0.5f) / 2.0f;
            inps[p * INP_S + 0] = 0.5f;
            inps[p * INP_S + 1] = 0.5f;
            inps[p * INP_S + 2] = ah - floorf(ah + 0.001f) - 0.5f;
            inps[p * INP_S + 3] = aw - floorf(aw + 0.001f) - 0.5f;
        }
        const float* xb = x + (size_t)bz * C * H * W;
        #pragma unroll 4
        for (int k = 0; k < 16; k++) {
            int c = cb * 16 + k;
            inps[p * INP_S + 4 + c] = bilin(xb + c * (H * W), fx, fy);
        }
    }
    __syncthreads();

    // ---- phase 2: layer1 (68 -> 64), relu ----
    {
        const int c  = t & 63;
        const int pb = t >> 6;
        const float* wrow = &w1s[c * 68];
        for (int j = 0; j < 4; j++) {
            int p0 = (pb << 4) + (j << 2);
            float a0 = b1s[c], a1 = a0, a2 = a0, a3 = a0;
            #pragma unroll
            for (int i4 = 0; i4 < 17; i4++) {
                float4 wv = ld4(wrow + i4 * 4);
                float4 v0 = ld4(&inps[(p0 + 0) * INP_S + i4 * 4]);
                float4 v1 = ld4(&inps[(p0 + 1) * INP_S + i4 * 4]);
                float4 v2 = ld4(&inps[(p0 + 2) * INP_S + i4 * 4]);
                float4 v3 = ld4(&inps[(p0 + 3) * INP_S + i4 * 4]);
                a0 += wv.x * v0.x + wv.y * v0.y + wv.z * v0.z + wv.w * v0.w;
                a1 += wv.x * v1.x + wv.y * v1.y + wv.z * v1.z + wv.w * v1.w;
                a2 += wv.x * v2.x + wv.y * v2.y + wv.z * v2.z + wv.w * v2.w;
                a3 += wv.x * v3.x + wv.y * v3.y + wv.z * v3.z + wv.w * v3.w;
            }
            hidf[(p0 + 0) * 64 + c] = fmaxf(a0, 0.0f);
            hidf[(p0 + 1) * 64 + c] = fmaxf(a1, 0.0f);
            hidf[(p0 + 2) * 64 + c] = fmaxf(a2, 0.0f);
            hidf[(p0 + 3) * 64 + c] = fmaxf(a3, 0.0f);
        }
    }
    __syncthreads();

    // ---- phase 3: layer2 (64 -> 64), relu -> embs (aliases inps) ----
    {
        const int c  = t & 63;
        const int pb = t >> 6;
        const float* wrow = &w2s[c * 68];
        for (int j = 0; j < 4; j++) {
            int p0 = (pb << 4) + (j << 2);
            float a0 = b2s[c], a1 = a0, a2 = a0, a3 = a0;
            #pragma unroll
            for (int i4 = 0; i4 < 16; i4++) {
                float4 wv = ld4(wrow + i4 * 4);
                float4 v0 = ld4(&hidf[(p0 + 0) * 64 + i4 * 4]);
                float4 v1 = ld4(&hidf[(p0 + 1) * 64 + i4 * 4]);
                float4 v2 = ld4(&hidf[(p0 + 2) * 64 + i4 * 4]);
                float4 v3 = ld4(&hidf[(p0 + 3) * 64 + i4 * 4]);
                a0 += wv.x * v0.x + wv.y * v0.y + wv.z * v0.z + wv.w * v0.w;
                a1 += wv.x * v1.x + wv.y * v1.y + wv.z * v1.z + wv.w * v1.w;
                a2 += wv.x * v2.x + wv.y * v2.y + wv.z * v2.z + wv.w * v2.w;
                a3 += wv.x * v3.x + wv.y * v3.y + wv.z * v3.z + wv.w * v3.w;
            }
            // NOTE: embs aliases inps; all inps reads finished at the sync above
            embs[(p0 + 0) * EMB_S + c] = fmaxf(a0, 0.0f);
            embs[(p0 + 1) * EMB_S + c] = fmaxf(a1, 0.0f);
            embs[(p0 + 2) * EMB_S + c] = fmaxf(a2, 0.0f);
            embs[(p0 + 3) * EMB_S + c] = fmaxf(a3, 0.0f);
        }
    }
    __syncthreads();

    // ---- phase 4: r (sigmoid) + offsets ----
    {
        const int e = t & 3;
        const int p = t >> 2;
        float accR = brs[e];
        float accO = (e < 2) ? bos[e] : 0.0f;
        const float* wop = (e < 2) ? &woTs[e] : &woTs[0];
        #pragma unroll 8
        for (int i = 0; i < 64; i++) {
            float ev = embs[p * EMB_S + i];
            accR += wrTs[i * 4 + e] * ev;
            accO += wop[i * 2] * ev;
        }
        rs[p * 5 + e] = 1.0f / (1.0f + __expf(-accR));
        if (e < 2) offs[p * 3 + e] = accO;
    }
    __syncthreads();

    // ---- phase 5: fea0 sample (with offsets) -> hidf (stride 68) ----
    {
        const int p  = t & 63;
        const int cb = t >> 6;
        const int ox = ox0 + p;
        float gx = ((ox + 0.5f) / 2.0f - 0.5f) * inv127 - 1.0f;
        float gy = ((oy + 0.5f) / 2.0f - 0.5f) * inv127 - 1.0f;
        float ix = gx + offs[p * 3 + 0] * inv127;
        float iy = gy + offs[p * 3 + 1] * inv127;
        float fx = ((ix + 1.0f) * (float)W - 1.0f) * 0.5f;
        float fy = ((iy + 1.0f) * (float)H - 1.0f) * 0.5f;
        const float* xb = x + (size_t)bz * C * H * W;
        #pragma unroll 4
        for (int k = 0; k < 16; k++) {
            int c = cb * 16 + k;
            hidf[p * FEA_S + c] = bilin(xb + c * (H * W), fx, fy);
        }
    }
    __syncthreads();

    // ---- phase 6: compress: t[e][d] = wc[e,d,:]·fea0, comp[d] = sum_e r_e t[e][d] ----
    {
        const int lane = t & 31;
        const int wid  = t >> 5;
        const int e = lane >> 3;
        const float* wrow = &wcp[lane * 68];
        for (int j = 0; j < 2; j++) {
            int p0 = wid * 8 + j * 4;
            float a0 = 0.0f, a1 = 0.0f, a2 = 0.0f, a3 = 0.0f;
            #pragma unroll
            for (int c4 = 0; c4 < 16; c4++) {
                float4 wv = ld4(wrow + c4 * 4);
                float4 v0 = ld4(&hidf[(p0 + 0) * FEA_S + c4 * 4]);
                float4 v1 = ld4(&hidf[(p0 + 1) * FEA_S + c4 * 4]);
                float4 v2 = ld4(&hidf[(p0 + 2) * FEA_S + c4 * 4]);
                float4 v3 = ld4(&hidf[(p0 + 3) * FEA_S + c4 * 4]);
                a0 += wv.x * v0.x + wv.y * v0.y + wv.z * v0.z + wv.w * v0.w;
                a1 += wv.x * v1.x + wv.y * v1.y + wv.z * v1.z + wv.w * v1.w;
                a2 += wv.x * v2.x + wv.y * v2.y + wv.z * v2.z + wv.w * v2.w;
                a3 += wv.x * v3.x + wv.y * v3.y + wv.z * v3.z + wv.w * v3.w;
            }
            float acc[4] = {a0, a1, a2, a3};
            #pragma unroll
            for (int q = 0; q < 4; q++) {
                float v = acc[q] * rs[(p0 + q) * 5 + e];
                v += __shfl_xor_sync(0xFFFFFFFFu, v, 8);
                v += __shfl_xor_sync(0xFFFFFFFFu, v, 16);
                if (lane < 8) cmps[(p0 + q) * 9 + lane] = v;
            }
        }
    }
    __syncthreads();

    // ---- phase 7: expand + residual + store ----
    {
        const int p  = t & 63;
        const int cb = t >> 6;
        float cr[8];
        #pragma unroll
        for (int d = 0; d < 8; d++) cr[d] = cmps[p * 9 + d];
        float rr[4];
        #pragma unroll
        for (int e = 0; e < 4; e++) rr[e] = rs[p * 5 + e];
        const int ox = ox0 + p;
        #pragma unroll 2
        for (int k = 0; k < 16; k++) {
            int c = cb * 16 + k;
            float acc = hidf[p * FEA_S + c];
            #pragma unroll
            for (int e = 0; e < 4; e++) {
                const float* werow = &wes[(e * 64 + c) * 8];
                float4 aa = ld4(werow);
                float4 bb = ld4(werow + 4);
                float s = aa.x * cr[0] + aa.y * cr[1] + aa.z * cr[2] + aa.w * cr[3]
                        + bb.x * cr[4] + bb.y * cr[5] + bb.z * cr[6] + bb.w * cr[7];
                acc += rr[e] * s;
            }
            out[(((size_t)bz * C + c) * OUT + oy) * OUT + ox] = acc;
        }
    }
}

extern "C" void kernel_launch(void* const* d_in, const int* in_sizes, int n_in,
                              void* d_out, int out_size) {
    (void)in_sizes; (void)n_in; (void)out_size;
    const float* x    = (const float*)d_in[0];
    const float* wcmp = (const float*)d_in[1];
    const float* wexp = (const float*)d_in[2];
    const float* w1   = (const float*)d_in[3];
    const float* b1   = (const float*)d_in[4];
    const float* w2   = (const float*)d_in[5];
    const float* b2   = (const float*)d_in[6];
    const float* wr   = (const float*)d_in[7];
    const float* br   = (const float*)d_in[8];
    const float* wo   = (const float*)d_in[9];
    const float* bo   = (const float*)d_in[10];
    float* out = (float*)d_out;

    cudaFuncSetAttribute(SCAB_upsample_20650202759886_kernel,
                         cudaFuncAttributeMaxDynamicSharedMemorySize, SMEM_BYTES);
    dim3 grid(OUT / TILE, OUT, Bz);
    SCAB_upsample_20650202759886_kernel<<<grid, NTHR, SMEM_BYTES>>>(
        x, wcmp, wexp, w1, b1, w2, b2, wr, br, wo, bo, out);
}

// round 2
// speedup vs baseline: 1.0767x; 1.0767x over previous
#include <cuda_runtime.h>
#include <cuda_bf16.h>
#include <math.h>

// Problem constants (fixed by setup_inputs)
#define Bz   2
#define C    64
#define H    128
#define W    128
#define OUT  256
#define TILE 64          // pixels per block (one row segment)
#define NTHR 256

// smem layout (in floats)
#define OFF_W1   0        // w1s[c*68+i],   64x68 = 4352
#define OFF_W2   4352     // w2s[c*68+i],   64x68 = 4352 (only 64 cols valid)
#define OFF_WC   8704     // wcp[(e*8+d)*68+c], 32x68 = 2176
#define OFF_WE   10880    // wes[(e*64+c)*8+d], 2048 (original layout)
#define OFF_WR   12928    // wrs[e*68+i],   4x68 = 272
#define OFF_WO   13200    // wos[o*68+i],   2x68 = 136
#define OFF_B1   13336    // 64
#define OFF_B2   13400    // 64
#define OFF_BR   13464    // 4
#define OFF_BO   13468    // 2 (+pad)
#define OFF_INP  13472    // inps[p*76+i], 64x76 = 4864 (aliased: embs[p*68+i])
#define OFF_HID  18336    // hidden[p*68+c] / fea0[p*68+c], 64x68 = 4352
#define OFF_RS   22688    // rs[p*8+e], 512
#define OFF_OFS  23200    // offs[p*2+o], 128
#define OFF_CMP  23328    // cmps[p*12+d], 768
#define SMEM_FLOATS 24096
#define SMEM_BYTES (SMEM_FLOATS * 4)

#define INP_S 76
#define EMB_S 68
#define FEA_S 68

typedef unsigned long long u64t;

__device__ __forceinline__ u64t fma2(u64t a, u64t b, u64t c) {
    u64t d;
    asm("fma.rn.f32x2 %0, %1, %2, %3;" : "=l"(d) : "l"(a), "l"(b), "l"(c));
    return d;
}
__device__ __forceinline__ float hadd2(u64t v) {
    float lo, hi;
    asm("mov.b64 {%0, %1}, %2;" : "=f"(lo), "=f"(hi) : "l"(v));
    return lo + hi;
}
__device__ __forceinline__ float4 ld4(const float* p) {
    return *reinterpret_cast<const float4*>(p);
}
__device__ __forceinline__ ulonglong2 ld2u(const float* p) {
    return *reinterpret_cast<const ulonglong2*>(p);
}

__device__ __forceinline__ float bilin(const float* __restrict__ img, float fx, float fy) {
    float x0f = floorf(fx), y0f = floorf(fy);
    float wx1 = fx - x0f, wy1 = fy - y0f;
    float wx0 = 1.0f - wx1, wy0 = 1.0f - wy1;
    int x0 = (int)x0f, y0 = (int)y0f;
    int xi0 = min(max(x0, 0), W - 1), yi0 = min(max(y0, 0), H - 1);
    int xi1 = min(max(x0 + 1, 0), W - 1), yi1 = min(max(y0 + 1, 0), H - 1);
    bool vx0 = (x0f >= 0.0f) && (x0f <= (float)(W - 1));
    bool vx1 = (x0f >= -1.0f) && (x0f <= (float)(W - 2));
    bool vy0 = (y0f >= 0.0f) && (y0f <= (float)(H - 1));
    bool vy1 = (y0f >= -1.0f) && (y0f <= (float)(H - 2));
    float v00 = (vx0 && vy0) ? __ldg(img + yi0 * W + xi0) : 0.0f;
    float v10 = (vx1 && vy0) ? __ldg(img + yi0 * W + xi1) : 0.0f;
    float v01 = (vx0 && vy1) ? __ldg(img + yi1 * W + xi0) : 0.0f;
    float v11 = (vx1 && vy1) ? __ldg(img + yi1 * W + xi1) : 0.0f;
    return v00 * (wx0 * wy0) + v10 * (wx1 * wy0) + v01 * (wx0 * wy1) + v11 * (wx1 * wy1);
}

__global__ __launch_bounds__(NTHR, 2)
void SCAB_upsample_20650202759886_kernel(
    const float* __restrict__ x,
    const float* __restrict__ wcmp,   // (4,8,64)
    const float* __restrict__ wexp,   // (4,64,8)
    const float* __restrict__ w1,     // (64,68)
    const float* __restrict__ b1,
    const float* __restrict__ w2,     // (64,64)
    const float* __restrict__ b2,
    const float* __restrict__ wr,     // (4,64)
    const float* __restrict__ br,
    const float* __restrict__ wo,     // (2,64)
    const float* __restrict__ bo,
    float* __restrict__ out)
{
    extern __shared__ float sm[];
    float* w1s  = sm + OFF_W1;
    float* w2s  = sm + OFF_W2;
    float* wcp  = sm + OFF_WC;
    float* wes  = sm + OFF_WE;
    float* wrs  = sm + OFF_WR;
    float* wos  = sm + OFF_WO;
    float* b1s  = sm + OFF_B1;
    float* b2s  = sm + OFF_B2;
    float* brs  = sm + OFF_BR;
    float* bos  = sm + OFF_BO;
    float* inps = sm + OFF_INP;   // also embs (stride 68) after phase 3
    float* embs = sm + OFF_INP;
    float* hidf = sm + OFF_HID;   // hidden / fea0 union (stride 68)
    float* rs   = sm + OFF_RS;
    float* offs = sm + OFF_OFS;
    float* cmps = sm + OFF_CMP;

    const int t  = threadIdx.x;
    const int oy = blockIdx.y;
    const int bz = blockIdx.z;
    const int ox0 = blockIdx.x * TILE;

    // ---- stage weights ----
    for (int i = t; i < 64 * 68; i += NTHR) w1s[i] = w1[i];
    for (int i = t; i < 64 * 64; i += NTHR) { int c = i >> 6, k = i & 63; w2s[c * 68 + k] = w2[i]; }
    for (int i = t; i < 32 * 64; i += NTHR) { int ed = i >> 6, c = i & 63; wcp[ed * 68 + c] = wcmp[i]; }
    for (int i = t; i < 2048;    i += NTHR) wes[i] = wexp[i];
    if (t < 256) { int e = t >> 6, k = t & 63; wrs[e * 68 + k] = wr[t]; }
    if (t < 128) { int o = t >> 6, k = t & 63; wos[o * 68 + k] = wo[t]; }
    if (t < 64) { b1s[t] = b1[t]; b2s[t] = b2[t]; }
    if (t < 4) brs[t] = br[t];
    if (t < 2) bos[t] = bo[t];
    __syncthreads();

    const float inv127 = 2.0f / 127.0f;

    // ---- phase 1: coords + pre_fea sample -> inps (stride 76) ----
    {
        const int p  = t & 63;
        const int cb = t >> 6;
        const int ox = ox0 + p;
        float gx = ((ox + 0.5f) / 2.0f - 0.5f) * inv127 - 1.0f;
        float gy = ((oy + 0.5f) / 2.0f - 0.5f) * inv127 - 1.0f;
        float fx = ((gx + 1.0f) * (float)W - 1.0f) * 0.5f;
        float fy = ((gy + 1.0f) * (float)H - 1.0f) * 0.5f;
        if (cb == 0) {
            float ah = (oy + 0.5f) / 2.0f;
            float aw = (ox + 0.5f) / 2.0f;
            inps[p * INP_S + 0] = 0.5f;
            inps[p * INP_S + 1] = 0.5f;
            inps[p * INP_S + 2] = ah - floorf(ah + 0.001f) - 0.5f;
            inps[p * INP_S + 3] = aw - floorf(aw + 0.001f) - 0.5f;
        }
        const float* xb = x + (size_t)bz * C * H * W;
        #pragma unroll 4
        for (int k = 0; k < 16; k++) {
            int c = cb * 16 + k;
            inps[p * INP_S + 4 + c] = bilin(xb + c * (H * W), fx, fy);
        }
    }
    __syncthreads();

    // ---- phase 2: layer1 (68 -> 64), relu. thread = (pixel, 16-ch group).
    //      acts in regs, weights broadcast, f32x2 FMA ----
    {
        const int p = t & 63, g = t >> 6;
        ulonglong2 A[17];
        #pragma unroll
        for (int i = 0; i < 17; i++) A[i] = ld2u(&inps[p * INP_S + i * 4]);
        const float* wbase = w1s + g * 16 * 68;
        const float* bb    = b1s + g * 16;
        float* hrow = &hidf[p * 68 + g * 16];
        #pragma unroll 1
        for (int cc = 0; cc < 4; cc++) {
            float4 o4;
            #pragma unroll
            for (int c4 = 0; c4 < 4; c4++) {
                const float* wrow = wbase + (cc * 4 + c4) * 68;
                u64t a0 = 0ull, a1 = 0ull;
                #pragma unroll
                for (int i = 0; i < 17; i++) {
                    ulonglong2 wv = ld2u(wrow + i * 4);
                    a0 = fma2(wv.x, A[i].x, a0);
                    a1 = fma2(wv.y, A[i].y, a1);
                }
                float s = hadd2(a0) + hadd2(a1) + bb[cc * 4 + c4];
                ((float*)&o4)[c4] = fmaxf(s, 0.0f);
            }
            *reinterpret_cast<float4*>(hrow + cc * 4) = o4;
        }
    }
    __syncthreads();

    // ---- phase 3: layer2 (64 -> 64), relu -> embs (stride 68, aliases inps) ----
    {
        const int p = t & 63, g = t >> 6;
        ulonglong2 A[16];
        #pragma unroll
        for (int i = 0; i < 16; i++) A[i] = ld2u(&hidf[p * 68 + i * 4]);
        const float* wbase = w2s + g * 16 * 68;
        const float* bb    = b2s + g * 16;
        float erow[16];
        #pragma unroll 1
        for (int cc = 0; cc < 4; cc++) {
            #pragma unroll
            for (int c4 = 0; c4 < 4; c4++) {
                const float* wrow = wbase + (cc * 4 + c4) * 68;
                u64t a0 = 0ull, a1 = 0ull;
                #pragma unroll
                for (int i = 0; i < 16; i++) {
                    ulonglong2 wv = ld2u(wrow + i * 4);
                    a0 = fma2(wv.x, A[i].x, a0);
                    a1 = fma2(wv.y, A[i].y, a1);
                }
                float s = hadd2(a0) + hadd2(a1) + bb[cc * 4 + c4];
                erow[cc * 4 + c4] = fmaxf(s, 0.0f);
            }
        }
        // embs aliases inps; all inps reads finished at the sync above
        float* ebase = &embs[p * EMB_S + g * 16];
        #pragma unroll
        for (int cc = 0; cc < 4; cc++)
            *reinterpret_cast<float4*>(ebase + cc * 4) =
                *reinterpret_cast<const float4*>(&erow[cc * 4]);
    }
    __syncthreads();

    // ---- phase 4: r (sigmoid) + offsets, f32x2 ----
    {
        const int p = t >> 2, e = t & 3;
        const float* erow = &embs[p * EMB_S];
        const float* wrr = wrs + e * 68;
        const float* wor = wos + (e & 1) * 68;
        u64t r0 = 0ull, r1 = 0ull, o0 = 0ull, o1 = 0ull;
        #pragma unroll
        for (int i = 0; i < 16; i++) {
            ulonglong2 ev  = ld2u(erow + i * 4);
            ulonglong2 wrv = ld2u(wrr + i * 4);
            ulonglong2 wov = ld2u(wor + i * 4);
            r0 = fma2(wrv.x, ev.x, r0);
            r1 = fma2(wrv.y, ev.y, r1);
            o0 = fma2(wov.x, ev.x, o0);
            o1 = fma2(wov.y, ev.y, o1);
        }
        float accR = hadd2(r0) + hadd2(r1) + brs[e];
        rs[p * 8 + e] = 1.0f / (1.0f + __expf(-accR));
        if (e < 2) offs[p * 2 + e] = hadd2(o0) + hadd2(o1) + bos[e];
    }
    __syncthreads();

    // ---- phase 5: fea0 sample (with offsets) -> hidf (stride 68) ----
    {
        const int p  = t & 63;
        const int cb = t >> 6;
        const int ox = ox0 + p;
        float gx = ((ox + 0.5f) / 2.0f - 0.5f) * inv127 - 1.0f;
        float gy = ((oy + 0.5f) / 2.0f - 0.5f) * inv127 - 1.0f;
        float ix = gx + offs[p * 2 + 0] * inv127;
        float iy = gy + offs[p * 2 + 1] * inv127;
        float fx = ((ix + 1.0f) * (float)W - 1.0f) * 0.5f;
        float fy = ((iy + 1.0f) * (float)H - 1.0f) * 0.5f;
        const float* xb = x + (size_t)bz * C * H * W;
        #pragma unroll 4
        for (int k = 0; k < 16; k++) {
            int c = cb * 16 + k;
            hidf[p * FEA_S + c] = bilin(xb + c * (H * W), fx, fy);
        }
    }
    __syncthreads();

    // ---- phase 6: comp[d] = sum_e r_e * (wc[e,d,:]·fea0). thread = (pixel, d-pair) ----
    {
        const int p = t & 63, dg = t >> 6;   // d pair (2dg, 2dg+1)
        ulonglong2 Fv[16];
        #pragma unroll
        for (int i = 0; i < 16; i++) Fv[i] = ld2u(&hidf[p * FEA_S + i * 4]);
        float4 rv = ld4(&rs[p * 8]);
        float comp0 = 0.0f, comp1 = 0.0f;
        #pragma unroll
        for (int e = 0; e < 4; e++) {
            const float* w0 = &wcp[(e * 8 + 2 * dg) * 68];
            const float* w1r = w0 + 68;
            u64t a0 = 0ull, a1 = 0ull, c0 = 0ull, c1 = 0ull;
            #pragma unroll
            for (int i = 0; i < 16; i++) {
                ulonglong2 wv0 = ld2u(w0 + i * 4);
                ulonglong2 wv1 = ld2u(w1r + i * 4);
                a0 = fma2(wv0.x, Fv[i].x, a0);
                a1 = fma2(wv0.y, Fv[i].y, a1);
                c0 = fma2(wv1.x, Fv[i].x, c0);
                c1 = fma2(wv1.y, Fv[i].y, c1);
            }
            float re = ((const float*)&rv)[e];
            comp0 = fmaf(re, hadd2(a0) + hadd2(a1), comp0);
            comp1 = fmaf(re, hadd2(c0) + hadd2(c1), comp1);
        }
        cmps[p * 12 + 2 * dg]     = comp0;
        cmps[p * 12 + 2 * dg + 1] = comp1;
    }
    __syncthreads();

    // ---- phase 7: expand + residual + store, f32x2 ----
    {
        const int p  = t & 63;
        const int cb = t >> 6;
        ulonglong2 cr0 = ld2u(&cmps[p * 12]);
        ulonglong2 cr1 = ld2u(&cmps[p * 12 + 4]);
        float4 rv = ld4(&rs[p * 8]);
        const int ox = ox0 + p;
        float* ob = out + (((size_t)bz * C + cb * 16) * OUT + oy) * OUT + ox;
        #pragma unroll 1
        for (int k4 = 0; k4 < 4; k4++) {
            float4 f4 = ld4(&hidf[p * FEA_S + cb * 16 + k4 * 4]);
            #pragma unroll
            for (int kk = 0; kk < 4; kk++) {
                int c = cb * 16 + k4 * 4 + kk;
                float acc = ((const float*)&f4)[kk];
                #pragma unroll
                for (int e = 0; e < 4; e++) {
                    const float* werow = &wes[(e * 64 + c) * 8];
                    ulonglong2 wv = ld2u(werow);
                    ulonglong2 wv2 = ld2u(werow + 4);
                    u64t s2 = fma2(wv.x, cr0.x, 0ull);
                    s2 = fma2(wv.y, cr0.y, s2);
                    s2 = fma2(wv2.x, cr1.x, s2);
                    s2 = fma2(wv2.y, cr1.y, s2);
                    acc = fmaf(((const float*)&rv)[e], hadd2(s2), acc);
                }
                ob[(size_t)(k4 * 4 + kk) * OUT * OUT] = acc;
            }
        }
    }
}

extern "C" void kernel_launch(void* const* d_in, const int* in_sizes, int n_in,
                              void* d_out, int out_size) {
    (void)in_sizes; (void)n_in; (void)out_size;
    const float* x    = (const float*)d_in[0];
    const float* wcmp = (const float*)d_in[1];
    const float* wexp = (const float*)d_in[2];
    const float* w1   = (const float*)d_in[3];
    const float* b1   = (const float*)d_in[4];
    const float* w2   = (const float*)d_in[5];
    const float* b2   = (const float*)d_in[6];
    const float* wr   = (const float*)d_in[7];
    const float* br   = (const float*)d_in[8];
    const float* wo   = (const float*)d_in[9];
    const float* bo   = (const float*)d_in[10];
    float* out = (float*)d_out;

    cudaFuncSetAttribute(SCAB_upsample_20650202759886_kernel,
                         cudaFuncAttributeMaxDynamicSharedMemorySize, SMEM_BYTES);
    dim3 grid(OUT / TILE, OUT, Bz);
    SCAB_upsample_20650202759886_kernel<<<grid, NTHR, SMEM_BYTES>>>(
        x, wcmp, wexp, w1, b1, w2, b2, wr, br, wo, bo, out);
}